// round 1
// baseline (speedup 1.0000x reference)
#include <cuda_runtime.h>
#include <cstdint>

#define H 768
#define NB 64
#define S1 513
#define S 512
#define NROWS (NB*S)   // 32768

// out layout (flattened tuple, float32):
// isqa_pred(64), crf_pred(32768), isqa_loss(1), crf_loss(1), tags(32768), IsQA(64)
#define OFF_ISQA_PRED 0
#define OFF_CRF_PRED  64
#define OFF_ISQA_LOSS (64+32768)
#define OFF_CRF_LOSS  (64+32768+1)
#define OFF_TAGS      (64+32768+2)
#define OFF_ISQA      (64+32768+2+32768)

__device__ __align__(16) float g_feats[NROWS*4];
__device__ float g_logits[2*NB];
__device__ float g_Z[NB];
__device__ float g_gold[NB];
__device__ __align__(128) unsigned char g_bp[NB*512];

// ---------------------------------------------------------------------------
// K1: feats GEMV (blocks 0..1023), cls GEMV (1024..1031), tag/IsQA copy (1032..1039)
// ---------------------------------------------------------------------------
__global__ __launch_bounds__(256) void k1(
    const float* __restrict__ emb, const int* __restrict__ asl,
    const int* __restrict__ isqa,
    const float* __restrict__ fc2W, const float* __restrict__ fc2b,
    const float* __restrict__ crfW, const float* __restrict__ crfb,
    float* __restrict__ out)
{
    const int bx = blockIdx.x;
    const int lane = threadIdx.x & 31;
    const int winb = threadIdx.x >> 5;

    if (bx < 1024) {
        // warp handles 4 rows of feats
        const int warp = bx * 8 + winb;
        const int row0 = warp * 4;
        // crf_W register-resident: w[k][c][t], h = k*128 + lane*4 + c
        float w[6][4][4];
        #pragma unroll
        for (int k = 0; k < 6; k++) {
            const int h = k * 128 + lane * 4;
            #pragma unroll
            for (int t = 0; t < 4; t++) {
                float4 wv = *(const float4*)&crfW[t * H + h];
                w[k][0][t] = wv.x; w[k][1][t] = wv.y;
                w[k][2][t] = wv.z; w[k][3][t] = wv.w;
            }
        }
        int base[4];
        #pragma unroll
        for (int r = 0; r < 4; r++) {
            const int row = row0 + r;
            const int b = row >> 9, s = row & 511;
            base[r] = (b * S1 + s + 1) * H;
        }
        float acc[4][4];
        #pragma unroll
        for (int r = 0; r < 4; r++)
            #pragma unroll
            for (int t = 0; t < 4; t++) acc[r][t] = 0.f;

        #pragma unroll
        for (int k = 0; k < 6; k++) {
            float4 e[4];
            #pragma unroll
            for (int r = 0; r < 4; r++)
                e[r] = *(const float4*)&emb[base[r] + k * 128 + lane * 4];
            #pragma unroll
            for (int r = 0; r < 4; r++) {
                const float ec[4] = { e[r].x, e[r].y, e[r].z, e[r].w };
                #pragma unroll
                for (int c = 0; c < 4; c++)
                    #pragma unroll
                    for (int t = 0; t < 4; t++)
                        acc[r][t] += ec[c] * w[k][c][t];
            }
        }
        #pragma unroll
        for (int r = 0; r < 4; r++)
            #pragma unroll
            for (int t = 0; t < 4; t++) {
                float v = acc[r][t];
                v += __shfl_xor_sync(0xffffffffu, v, 16);
                v += __shfl_xor_sync(0xffffffffu, v, 8);
                v += __shfl_xor_sync(0xffffffffu, v, 4);
                v += __shfl_xor_sync(0xffffffffu, v, 2);
                v += __shfl_xor_sync(0xffffffffu, v, 1);
                acc[r][t] = v;
            }
        if (lane < 4) {
            const int row = row0 + lane;
            float4 o;
            o.x = acc[lane][0] + crfb[0];
            o.y = acc[lane][1] + crfb[1];
            o.z = acc[lane][2] + crfb[2];
            o.w = acc[lane][3] + crfb[3];
            *(float4*)&g_feats[row * 4] = o;
        }
    } else if (bx < 1032) {
        // cls logits: warp per batch element
        const int b = (bx - 1024) * 8 + winb;
        float wa[6][4], wb[6][4];
        #pragma unroll
        for (int k = 0; k < 6; k++) {
            const int h = k * 128 + lane * 4;
            float4 va = *(const float4*)&fc2W[h];
            float4 vb = *(const float4*)&fc2W[H + h];
            wa[k][0] = va.x; wa[k][1] = va.y; wa[k][2] = va.z; wa[k][3] = va.w;
            wb[k][0] = vb.x; wb[k][1] = vb.y; wb[k][2] = vb.z; wb[k][3] = vb.w;
        }
        const int base = b * S1 * H;  // emb[:,0]
        float a0 = 0.f, a1 = 0.f;
        #pragma unroll
        for (int k = 0; k < 6; k++) {
            float4 e = *(const float4*)&emb[base + k * 128 + lane * 4];
            const float ec[4] = { e.x, e.y, e.z, e.w };
            #pragma unroll
            for (int c = 0; c < 4; c++) {
                a0 += ec[c] * wa[k][c];
                a1 += ec[c] * wb[k][c];
            }
        }
        #pragma unroll
        for (int o = 16; o > 0; o >>= 1) {
            a0 += __shfl_xor_sync(0xffffffffu, a0, o);
            a1 += __shfl_xor_sync(0xffffffffu, a1, o);
        }
        if (lane == 0) {
            g_logits[2 * b]     = a0 + fc2b[0];
            g_logits[2 * b + 1] = a1 + fc2b[1];
        }
    } else {
        // copies: tags + IsQA passthrough
        const int tid = (bx - 1032) * 256 + threadIdx.x;
        for (int i = tid; i < NROWS; i += 2048) {
            const int b = i >> 9, s = i & 511;
            out[OFF_TAGS + i] = (float)asl[b * S1 + 1 + s];
        }
        if (tid < NB) out[OFF_ISQA + tid] = (float)isqa[tid];
    }
}

// ---------------------------------------------------------------------------
// K2: block 0 = log-partition (linear domain), block 1 = viterbi, blocks 2-3 = gold
// ---------------------------------------------------------------------------
__global__ __launch_bounds__(256) void k2(
    const int* __restrict__ asl, const float* __restrict__ trans,
    float* __restrict__ out)
{
    const int bx = blockIdx.x;
    const int lane = threadIdx.x & 31;
    const int winb = threadIdx.x >> 5;

    if (bx == 0) {
        const int b = threadIdx.x;
        if (b >= NB) return;
        float E[4][4];
        #pragma unroll
        for (int i = 0; i < 4; i++)
            #pragma unroll
            for (int j = 0; j < 4; j++) E[i][j] = expf(trans[i * 4 + j]);
        const float4* fb = (const float4*)g_feats + b * 512;
        float4 f0 = __ldg(&fb[0]);
        const float x0 = f0.x + trans[8], x1 = f0.y + trans[9];
        const float x2 = f0.z + trans[10], x3 = f0.w + trans[11];
        float m = fmaxf(fmaxf(x0, x1), fmaxf(x2, x3));
        float a0 = __expf(x0 - m), a1 = __expf(x1 - m);
        float a2 = __expf(x2 - m), a3 = __expf(x3 - m);
        float logacc = m;

        #define PSTEP(f) {                                                   \
            const float e0 = __expf((f).x), e1 = __expf((f).y);              \
            const float e2 = __expf((f).z), e3 = __expf((f).w);              \
            const float n0 = ((a0*E[0][0] + a1*E[1][0]) + (a2*E[2][0] + a3*E[3][0])) * e0; \
            const float n1 = ((a0*E[0][1] + a1*E[1][1]) + (a2*E[2][1] + a3*E[3][1])) * e1; \
            const float n2 = ((a0*E[0][2] + a1*E[1][2]) + (a2*E[2][2] + a3*E[3][2])) * e2; \
            const float n3 = ((a0*E[0][3] + a1*E[1][3]) + (a2*E[2][3] + a3*E[3][3])) * e3; \
            a0 = n0; a1 = n1; a2 = n2; a3 = n3; }

        for (int c = 0; c < 63; c++) {
            float4 fr[8];
            #pragma unroll
            for (int u = 0; u < 8; u++) fr[u] = __ldg(&fb[c * 8 + 1 + u]);
            #pragma unroll
            for (int u = 0; u < 8; u++) PSTEP(fr[u]);
            const float mm = fmaxf(fmaxf(a0, a1), fmaxf(a2, a3));
            const float inv = __fdividef(1.f, mm);
            a0 *= inv; a1 *= inv; a2 *= inv; a3 *= inv;
            logacc += __logf(mm);
        }
        {
            float4 fr[7];
            #pragma unroll
            for (int u = 0; u < 7; u++) fr[u] = __ldg(&fb[505 + u]);
            #pragma unroll
            for (int u = 0; u < 7; u++) PSTEP(fr[u]);
        }
        const float zsum = a0 * E[0][3] + a1 * E[1][3] + a2 * E[2][3] + a3 * E[3][3];
        g_Z[b] = logacc + __logf(zsum);
        #undef PSTEP
    } else if (bx == 1) {
        const int b = threadIdx.x;
        if (b >= NB) return;
        float T[16];
        #pragma unroll
        for (int i = 0; i < 16; i++) T[i] = trans[i];
        const float4* fb = (const float4*)g_feats + b * 512;
        float4 f0 = __ldg(&fb[0]);
        float d0 = f0.x + T[8], d1 = f0.y + T[9], d2 = f0.z + T[10], d3 = f0.w + T[11];
        for (int t = 1; t < 512; t++) {
            float4 f = __ldg(&fb[t]);
            const float fa[4] = { f.x, f.y, f.z, f.w };
            float nd[4]; int bp[4];
            #pragma unroll
            for (int j = 0; j < 4; j++) {
                const float s0 = d0 + T[j], s1 = d1 + T[4 + j];
                const float s2 = d2 + T[8 + j], s3 = d3 + T[12 + j];
                float m01 = s0; int b01 = 0; if (s1 > m01) { m01 = s1; b01 = 1; }
                float m23 = s2; int b23 = 2; if (s3 > m23) { m23 = s3; b23 = 3; }
                float mm = m01; int bb = b01; if (m23 > mm) { mm = m23; bb = b23; }
                nd[j] = mm + fa[j]; bp[j] = bb;
            }
            d0 = nd[0]; d1 = nd[1]; d2 = nd[2]; d3 = nd[3];
            g_bp[b * 512 + t - 1] =
                (unsigned char)(bp[0] | (bp[1] << 2) | (bp[2] << 4) | (bp[3] << 6));
        }
        const float s0 = d0 + T[3], s1 = d1 + T[7], s2 = d2 + T[11], s3 = d3 + T[15];
        float mm = s0; int tag = 0;
        if (s1 > mm) { mm = s1; tag = 1; }
        if (s2 > mm) { mm = s2; tag = 2; }
        if (s3 > mm) { mm = s3; tag = 3; }
        out[OFF_CRF_PRED + b * 512 + 511] = (float)tag;
        // backtrace: chunked prefetch so only shift/mask stays on the chain
        for (int c = 7; c >= 0; c--) {
            uint32_t wds[16];
            #pragma unroll
            for (int i = 0; i < 16; i++)
                wds[i] = *(const uint32_t*)&g_bp[b * 512 + c * 64 + i * 4];
            #pragma unroll
            for (int i = 63; i >= 0; i--) {
                const int t = c * 64 + i;
                if (t > 510) continue;
                const unsigned byte = (wds[i >> 2] >> ((i & 3) * 8)) & 0xffu;
                tag = (byte >> (2 * tag)) & 3;
                out[OFF_CRF_PRED + b * 512 + t] = (float)tag;
            }
        }
    } else {
        // gold score: 16 warps, 4 batches each
        const int wg = (bx - 2) * 8 + winb;
        for (int q = 0; q < 4; q++) {
            const int b = wg * 4 + q;
            float s = 0.f;
            for (int i = lane; i < 512; i += 32) {
                const int tg = asl[b * S1 + 1 + i];
                s += g_feats[(b * 512 + i) * 4 + tg];
                if (i < 511) {
                    const int tg2 = asl[b * S1 + 2 + i];
                    s += trans[tg * 4 + tg2];
                }
            }
            if (lane == 0) {
                const int t0 = asl[b * S1 + 1];
                const int tl = asl[b * S1 + 512];
                s += trans[8 + t0] + trans[tl * 4 + 3];
            }
            #pragma unroll
            for (int o = 16; o > 0; o >>= 1) s += __shfl_xor_sync(0xffffffffu, s, o);
            if (lane == 0) g_gold[b] = s;
        }
    }
}

// ---------------------------------------------------------------------------
// K3: losses + isqa predictions
// ---------------------------------------------------------------------------
__global__ void k3(const int* __restrict__ isqa, float* __restrict__ out)
{
    __shared__ float sh[4];
    const int t = threadIdx.x;  // 64 threads
    float diff = 0.f, lossb = 0.f;
    if (t < NB) {
        diff = g_Z[t] - g_gold[t];
        const float l0 = g_logits[2 * t], l1 = g_logits[2 * t + 1];
        const float m = fmaxf(l0, l1);
        const float lse = m + __logf(__expf(l0 - m) + __expf(l1 - m));
        const int q = isqa[t];
        lossb = lse - (q ? l1 : l0);
        out[OFF_ISQA_PRED + t] = (l1 > l0) ? 1.0f : 0.0f;
    }
    #pragma unroll
    for (int o = 16; o > 0; o >>= 1) {
        diff  += __shfl_xor_sync(0xffffffffu, diff, o);
        lossb += __shfl_xor_sync(0xffffffffu, lossb, o);
    }
    if ((t & 31) == 0) { sh[(t >> 5) * 2] = diff; sh[(t >> 5) * 2 + 1] = lossb; }
    __syncthreads();
    if (t == 0) {
        out[OFF_CRF_LOSS]  = (sh[0] + sh[2]) * (1.0f / 64.0f);
        out[OFF_ISQA_LOSS] = (sh[1] + sh[3]) * (1.0f / 64.0f);
    }
}

extern "C" void kernel_launch(void* const* d_in, const int* in_sizes, int n_in,
                              void* d_out, int out_size)
{
    const float* emb  = (const float*)d_in[0];
    const int*   asl  = (const int*)d_in[1];
    const int*   isqa = (const int*)d_in[2];
    const float* fc2W = (const float*)d_in[3];
    const float* fc2b = (const float*)d_in[4];
    const float* crfW = (const float*)d_in[5];
    const float* crfb = (const float*)d_in[6];
    const float* trans= (const float*)d_in[7];
    float* out = (float*)d_out;

    k1<<<1040, 256>>>(emb, asl, isqa, fc2W, fc2b, crfW, crfb, out);
    k2<<<4, 256>>>(asl, trans, out);
    k3<<<1, 64>>>(isqa, out);
}

// round 2
// speedup vs baseline: 2.3659x; 2.3659x over previous
#include <cuda_runtime.h>
#include <cstdint>

#define H 768
#define NB 64
#define S1 513
#define S 512
#define NROWS (NB*S)   // 32768

// out layout (flattened tuple, float32):
// isqa_pred(64), crf_pred(32768), isqa_loss(1), crf_loss(1), tags(32768), IsQA(64)
#define OFF_ISQA_PRED 0
#define OFF_CRF_PRED  64
#define OFF_ISQA_LOSS (64+32768)
#define OFF_CRF_LOSS  (64+32768+1)
#define OFF_TAGS      (64+32768+2)
#define OFF_ISQA      (64+32768+2+32768)

__device__ __align__(16) float g_feats[NROWS*4 + 4];   // +4 pad for prefetch overrun
__device__ __align__(16) float g_efeats[NROWS*4 + 4];  // exp(feats), precomputed in k1
__device__ float g_logits[2*NB];
__device__ float g_Z[NB];
__device__ float g_gold[NB];
__device__ __align__(128) unsigned char g_bp[NB*512];

// ---------------------------------------------------------------------------
// K1: feats GEMV (blocks 0..1023, crfW in smem), cls GEMV (1024..1031),
//     tag/IsQA copy (1032..1039)
// ---------------------------------------------------------------------------
__global__ __launch_bounds__(256) void k1(
    const float* __restrict__ emb, const int* __restrict__ asl,
    const int* __restrict__ isqa,
    const float* __restrict__ fc2W, const float* __restrict__ fc2b,
    const float* __restrict__ crfW, const float* __restrict__ crfb,
    float* __restrict__ out)
{
    const int bx = blockIdx.x;
    const int lane = threadIdx.x & 31;
    const int winb = threadIdx.x >> 5;

    if (bx < 1024) {
        __shared__ float4 ws[768];  // ws[t*192 + j] = crfW[t][4j..4j+3]
        for (int i = threadIdx.x; i < 768; i += 256)
            ws[i] = ((const float4*)crfW)[i];
        __syncthreads();

        const int warp = bx * 8 + winb;
        const int row0 = warp * 4;
        int base[4];
        #pragma unroll
        for (int r = 0; r < 4; r++) {
            const int row = row0 + r;
            const int b = row >> 9, s = row & 511;
            base[r] = (b * S1 + s + 1) * H;
        }
        float acc[4][4];
        #pragma unroll
        for (int r = 0; r < 4; r++)
            #pragma unroll
            for (int t = 0; t < 4; t++) acc[r][t] = 0.f;

        #pragma unroll
        for (int k = 0; k < 6; k++) {
            float4 e[4];
            #pragma unroll
            for (int r = 0; r < 4; r++)
                e[r] = __ldg((const float4*)&emb[base[r] + k * 128 + lane * 4]);
            float4 w[4];
            #pragma unroll
            for (int t = 0; t < 4; t++)
                w[t] = ws[t * 192 + k * 32 + lane];
            #pragma unroll
            for (int r = 0; r < 4; r++)
                #pragma unroll
                for (int t = 0; t < 4; t++)
                    acc[r][t] += e[r].x * w[t].x + e[r].y * w[t].y
                               + e[r].z * w[t].z + e[r].w * w[t].w;
        }
        #pragma unroll
        for (int r = 0; r < 4; r++)
            #pragma unroll
            for (int t = 0; t < 4; t++) {
                float v = acc[r][t];
                v += __shfl_xor_sync(0xffffffffu, v, 16);
                v += __shfl_xor_sync(0xffffffffu, v, 8);
                v += __shfl_xor_sync(0xffffffffu, v, 4);
                v += __shfl_xor_sync(0xffffffffu, v, 2);
                v += __shfl_xor_sync(0xffffffffu, v, 1);
                acc[r][t] = v;
            }
        if (lane < 4) {
            const int row = row0 + lane;
            float4 o;
            o.x = acc[lane][0] + crfb[0];
            o.y = acc[lane][1] + crfb[1];
            o.z = acc[lane][2] + crfb[2];
            o.w = acc[lane][3] + crfb[3];
            *(float4*)&g_feats[row * 4] = o;
            float4 eo;
            eo.x = __expf(o.x); eo.y = __expf(o.y);
            eo.z = __expf(o.z); eo.w = __expf(o.w);
            *(float4*)&g_efeats[row * 4] = eo;
        }
    } else if (bx < 1032) {
        // cls logits: warp per batch element
        const int b = (bx - 1024) * 8 + winb;
        float wa[6][4], wb[6][4];
        #pragma unroll
        for (int k = 0; k < 6; k++) {
            const int h = k * 128 + lane * 4;
            float4 va = *(const float4*)&fc2W[h];
            float4 vb = *(const float4*)&fc2W[H + h];
            wa[k][0] = va.x; wa[k][1] = va.y; wa[k][2] = va.z; wa[k][3] = va.w;
            wb[k][0] = vb.x; wb[k][1] = vb.y; wb[k][2] = vb.z; wb[k][3] = vb.w;
        }
        const int base = b * S1 * H;  // emb[:,0]
        float a0 = 0.f, a1 = 0.f;
        #pragma unroll
        for (int k = 0; k < 6; k++) {
            float4 e = __ldg((const float4*)&emb[base + k * 128 + lane * 4]);
            const float ec[4] = { e.x, e.y, e.z, e.w };
            #pragma unroll
            for (int c = 0; c < 4; c++) {
                a0 += ec[c] * wa[k][c];
                a1 += ec[c] * wb[k][c];
            }
        }
        #pragma unroll
        for (int o = 16; o > 0; o >>= 1) {
            a0 += __shfl_xor_sync(0xffffffffu, a0, o);
            a1 += __shfl_xor_sync(0xffffffffu, a1, o);
        }
        if (lane == 0) {
            g_logits[2 * b]     = a0 + fc2b[0];
            g_logits[2 * b + 1] = a1 + fc2b[1];
        }
    } else {
        // copies: tags + IsQA passthrough
        const int tid = (bx - 1032) * 256 + threadIdx.x;
        for (int i = tid; i < NROWS; i += 2048) {
            const int b = i >> 9, s = i & 511;
            out[OFF_TAGS + i] = (float)asl[b * S1 + 1 + s];
        }
        if (tid < NB) out[OFF_ISQA + tid] = (float)isqa[tid];
    }
}

// ---------------------------------------------------------------------------
// K2: block 0 = log-partition (linear domain, exp precomputed),
//     block 1 = viterbi (pipelined), blocks 2-3 = gold
// ---------------------------------------------------------------------------
__global__ __launch_bounds__(256) void k2(
    const int* __restrict__ asl, const float* __restrict__ trans,
    float* __restrict__ out)
{
    const int bx = blockIdx.x;
    const int lane = threadIdx.x & 31;
    const int winb = threadIdx.x >> 5;

    if (bx == 0) {
        const int b = threadIdx.x;
        if (b >= NB) return;
        float E[4][4];
        #pragma unroll
        for (int i = 0; i < 4; i++)
            #pragma unroll
            for (int j = 0; j < 4; j++) E[i][j] = expf(trans[i * 4 + j]);
        const float4* fb = (const float4*)g_feats + b * 512;
        const float4* eb = (const float4*)g_efeats + b * 512;
        float4 f0 = __ldg(&fb[0]);
        const float x0 = f0.x + trans[8], x1 = f0.y + trans[9];
        const float x2 = f0.z + trans[10], x3 = f0.w + trans[11];
        float m = fmaxf(fmaxf(x0, x1), fmaxf(x2, x3));
        float a0 = __expf(x0 - m), a1 = __expf(x1 - m);
        float a2 = __expf(x2 - m), a3 = __expf(x3 - m);
        float logacc = m;

        #define PSTEP(f) {                                                   \
            const float n0 = ((a0*E[0][0] + a1*E[1][0]) + (a2*E[2][0] + a3*E[3][0])) * (f).x; \
            const float n1 = ((a0*E[0][1] + a1*E[1][1]) + (a2*E[2][1] + a3*E[3][1])) * (f).y; \
            const float n2 = ((a0*E[0][2] + a1*E[1][2]) + (a2*E[2][2] + a3*E[3][2])) * (f).z; \
            const float n3 = ((a0*E[0][3] + a1*E[1][3]) + (a2*E[2][3] + a3*E[3][3])) * (f).w; \
            a0 = n0; a1 = n1; a2 = n2; a3 = n3; }

        float4 cur[8];
        #pragma unroll
        for (int u = 0; u < 8; u++) cur[u] = __ldg(&eb[1 + u]);
        for (int c = 0; c < 63; c++) {
            float4 nxt[8];
            if (c < 62) {
                #pragma unroll
                for (int u = 0; u < 8; u++) nxt[u] = __ldg(&eb[c * 8 + 9 + u]);
            } else {
                #pragma unroll
                for (int u = 0; u < 7; u++) nxt[u] = __ldg(&eb[505 + u]);
                nxt[7] = make_float4(0.f, 0.f, 0.f, 0.f);
            }
            #pragma unroll
            for (int u = 0; u < 8; u++) PSTEP(cur[u]);
            const float mm = fmaxf(fmaxf(a0, a1), fmaxf(a2, a3));
            const float inv = __fdividef(1.f, mm);
            a0 *= inv; a1 *= inv; a2 *= inv; a3 *= inv;
            logacc += __logf(mm);
            #pragma unroll
            for (int u = 0; u < 8; u++) cur[u] = nxt[u];
        }
        #pragma unroll
        for (int u = 0; u < 7; u++) PSTEP(cur[u]);
        const float zsum = a0 * E[0][3] + a1 * E[1][3] + a2 * E[2][3] + a3 * E[3][3];
        g_Z[b] = logacc + __logf(zsum);
        #undef PSTEP
    } else if (bx == 1) {
        const int b = threadIdx.x;
        if (b >= NB) return;
        float T[16];
        #pragma unroll
        for (int i = 0; i < 16; i++) T[i] = trans[i];
        const float4* fb = (const float4*)g_feats + b * 512;
        float4 f0 = __ldg(&fb[0]);
        float d0 = f0.x + T[8], d1 = f0.y + T[9], d2 = f0.z + T[10], d3 = f0.w + T[11];

        float4 cur[8];
        #pragma unroll
        for (int u = 0; u < 8; u++) cur[u] = __ldg(&fb[1 + u]);
        for (int c = 0; c < 64; c++) {
            float4 nxt[8];
            if (c < 63) {
                #pragma unroll
                for (int u = 0; u < 8; u++) nxt[u] = __ldg(&fb[c * 8 + 9 + u]);
            } else {
                #pragma unroll
                for (int u = 0; u < 8; u++) nxt[u] = cur[u];
            }
            unsigned long long bpacc = 0ull;
            #pragma unroll
            for (int u = 0; u < 8; u++) {
                if (c < 63 || u < 7) {
                    const float4 f = cur[u];
                    const float fa[4] = { f.x, f.y, f.z, f.w };
                    float nd[4];
                    unsigned byte = 0;
                    #pragma unroll
                    for (int j = 0; j < 4; j++) {
                        const float s0 = d0 + T[j],     s1 = d1 + T[4 + j];
                        const float s2 = d2 + T[8 + j], s3 = d3 + T[12 + j];
                        const float m01 = fmaxf(s0, s1);
                        const float m23 = fmaxf(s2, s3);
                        nd[j] = fmaxf(m01, m23) + fa[j];
                        const int bb = (m23 > m01) ? (2 + (int)(s3 > s2))
                                                   : (int)(s1 > s0);
                        byte |= (unsigned)bb << (2 * j);
                    }
                    d0 = nd[0]; d1 = nd[1]; d2 = nd[2]; d3 = nd[3];
                    bpacc |= (unsigned long long)byte << (8 * u);
                }
            }
            *(uint2*)&g_bp[b * 512 + c * 8] =
                make_uint2((unsigned)bpacc, (unsigned)(bpacc >> 32));
            #pragma unroll
            for (int u = 0; u < 8; u++) cur[u] = nxt[u];
        }
        const float s0 = d0 + T[3], s1 = d1 + T[7], s2 = d2 + T[11], s3 = d3 + T[15];
        float mm = s0; int tag = 0;
        if (s1 > mm) { mm = s1; tag = 1; }
        if (s2 > mm) { mm = s2; tag = 2; }
        if (s3 > mm) { mm = s3; tag = 3; }
        out[OFF_CRF_PRED + b * 512 + 511] = (float)tag;
        // backtrace: chunked prefetch so only shift/mask stays on the chain
        for (int c = 7; c >= 0; c--) {
            uint32_t wds[16];
            #pragma unroll
            for (int i = 0; i < 16; i++)
                wds[i] = *(const uint32_t*)&g_bp[b * 512 + c * 64 + i * 4];
            #pragma unroll
            for (int i = 63; i >= 0; i--) {
                const int t = c * 64 + i;
                if (t > 510) continue;
                const unsigned byte = (wds[i >> 2] >> ((i & 3) * 8)) & 0xffu;
                tag = (byte >> (2 * tag)) & 3;
                out[OFF_CRF_PRED + b * 512 + t] = (float)tag;
            }
        }
    } else {
        // gold score: 16 warps, 4 batches each
        const int wg = (bx - 2) * 8 + winb;
        for (int q = 0; q < 4; q++) {
            const int b = wg * 4 + q;
            float s = 0.f;
            for (int i = lane; i < 512; i += 32) {
                const int tg = asl[b * S1 + 1 + i];
                s += g_feats[(b * 512 + i) * 4 + tg];
                if (i < 511) {
                    const int tg2 = asl[b * S1 + 2 + i];
                    s += trans[tg * 4 + tg2];
                }
            }
            if (lane == 0) {
                const int t0 = asl[b * S1 + 1];
                const int tl = asl[b * S1 + 512];
                s += trans[8 + t0] + trans[tl * 4 + 3];
            }
            #pragma unroll
            for (int o = 16; o > 0; o >>= 1) s += __shfl_xor_sync(0xffffffffu, s, o);
            if (lane == 0) g_gold[b] = s;
        }
    }
}

// ---------------------------------------------------------------------------
// K3: losses + isqa predictions
// ---------------------------------------------------------------------------
__global__ void k3(const int* __restrict__ isqa, float* __restrict__ out)
{
    __shared__ float sh[4];
    const int t = threadIdx.x;  // 64 threads
    float diff = 0.f, lossb = 0.f;
    if (t < NB) {
        diff = g_Z[t] - g_gold[t];
        const float l0 = g_logits[2 * t], l1 = g_logits[2 * t + 1];
        const float m = fmaxf(l0, l1);
        const float lse = m + __logf(__expf(l0 - m) + __expf(l1 - m));
        const int q = isqa[t];
        lossb = lse - (q ? l1 : l0);
        out[OFF_ISQA_PRED + t] = (l1 > l0) ? 1.0f : 0.0f;
    }
    #pragma unroll
    for (int o = 16; o > 0; o >>= 1) {
        diff  += __shfl_xor_sync(0xffffffffu, diff, o);
        lossb += __shfl_xor_sync(0xffffffffu, lossb, o);
    }
    if ((t & 31) == 0) { sh[(t >> 5) * 2] = diff; sh[(t >> 5) * 2 + 1] = lossb; }
    __syncthreads();
    if (t == 0) {
        out[OFF_CRF_LOSS]  = (sh[0] + sh[2]) * (1.0f / 64.0f);
        out[OFF_ISQA_LOSS] = (sh[1] + sh[3]) * (1.0f / 64.0f);
    }
}

extern "C" void kernel_launch(void* const* d_in, const int* in_sizes, int n_in,
                              void* d_out, int out_size)
{
    const float* emb  = (const float*)d_in[0];
    const int*   asl  = (const int*)d_in[1];
    const int*   isqa = (const int*)d_in[2];
    const float* fc2W = (const float*)d_in[3];
    const float* fc2b = (const float*)d_in[4];
    const float* crfW = (const float*)d_in[5];
    const float* crfb = (const float*)d_in[6];
    const float* trans= (const float*)d_in[7];
    float* out = (float*)d_out;

    k1<<<1040, 256>>>(emb, asl, isqa, fc2W, fc2b, crfW, crfb, out);
    k2<<<4, 256>>>(asl, trans, out);
    k3<<<1, 64>>>(isqa, out);
}